// round 7
// baseline (speedup 1.0000x reference)
#include <cuda_runtime.h>
#include <cuda_bf16.h>
#include <math.h>

// Shapes (fixed by the problem)
//  emb_in [512,768], W1 [256,1536], b1[256], W2 [256,256], b2[256], W3[1,256], b3[1]
#define B_ROWS 512
#define D_DIM  768
#define H_DIM  256
#define N_CON  128      // n = B/4
#define M_POS  256      // m = B/2
#define NPAIRS 57280.0f

// ---------------- device scratch (statically allocated: no cudaMalloc) -----
__device__ float g_z[B_ROWS * D_DIM];              // normalized rows (f32, contrastive)
__device__ __nv_bfloat16 g_zh[B_ROWS * D_DIM];     // normalized rows (bf16, proj)
__device__ __nv_bfloat16 g_W1h[H_DIM * 2 * D_DIM]; // W1 bf16, natural [n][1536]
__device__ __nv_bfloat16 g_W2h[H_DIM * H_DIM];     // W2 bf16, natural [n][k]
__device__ __nv_bfloat16 g_Ah[N_CON * H_DIM];      // (z[:128] @ W1a.T + b1) bf16
__device__ __nv_bfloat16 g_Bh[B_ROWS * H_DIM];     // (z @ W1b.T) bf16
__device__ float g_lp[2][N_CON][B_ROWS];           // logit partials per N-half
__device__ float g_cpart[N_CON];                   // contrastive partials per i
__device__ float g_epart[N_CON];                   // bce partials per i

// ---------------- kernel 1: L2 normalize rows (f32 + bf16 out) ---------------
__global__ __launch_bounds__(256) void normalize_kernel(const float* __restrict__ emb) {
    int row = blockIdx.x, tid = threadIdx.x, lane = tid & 31, wid = tid >> 5;
    const float* r = emb + row * D_DIM;
    float s = 0.f;
    for (int k = tid; k < D_DIM; k += 256) { float v = r[k]; s += v * v; }
    #pragma unroll
    for (int o = 16; o; o >>= 1) s += __shfl_xor_sync(0xffffffffu, s, o);
    __shared__ float red[8];
    __shared__ float rn;
    if (lane == 0) red[wid] = s;
    __syncthreads();
    if (tid == 0) {
        float t = 0.f;
        #pragma unroll
        for (int w = 0; w < 8; ++w) t += red[w];
        rn = 1.0f / fmaxf(sqrtf(t), 1e-12f);
    }
    __syncthreads();
    float rnv = rn;
    for (int k = tid; k < D_DIM; k += 256) {
        float v = r[k] * rnv;
        g_z[row * D_DIM + k] = v;
        g_zh[row * D_DIM + k] = __float2bfloat16(v);
    }
}

// ---------------- kernel 2: convert W1, W2 to bf16 (coalesced, no transpose)
__global__ __launch_bounds__(256) void prep_kernel(const float* __restrict__ W1,
                                                   const float* __restrict__ W2) {
    int b = blockIdx.x, tid = threadIdx.x;
    if (b < 1536) {
        int idx = b * 256 + tid;
        g_W1h[idx] = __float2bfloat16(W1[idx]);
    } else {
        int idx = (b - 1536) * 256 + tid;
        g_W2h[idx] = __float2bfloat16(W2[idx]);
    }
}

// ---------------- kernel 3: contrastive per-row (f32) ------------------------
// cpart[i] = (n-1-i)*log(sum_{k!=i} exp(2 S[i,k])) - sum_{j in (i,128)} 2 S[i,j]
__global__ __launch_bounds__(256) void contrastive_kernel() {
    __shared__ float zi[D_DIM];
    __shared__ float wden[8], wls[8];
    int i = blockIdx.x, tid = threadIdx.x, lane = tid & 31, wid = tid >> 5;
    for (int k = tid; k < D_DIM; k += 256) zi[k] = g_z[i * D_DIM + k];
    __syncthreads();
    float den = 0.f, ls = 0.f;
    for (int j = wid; j < B_ROWS; j += 8) {
        float s = 0.f;
        #pragma unroll
        for (int t = 0; t < D_DIM / 32; ++t) {
            int k = lane + t * 32;
            s += g_z[j * D_DIM + k] * zi[k];
        }
        #pragma unroll
        for (int o = 16; o; o >>= 1) s += __shfl_xor_sync(0xffffffffu, s, o);
        float l = 2.0f * s;
        if (j != i) den += expf(l);
        if (j > i && j < N_CON) ls += l;
    }
    if (lane == 0) { wden[wid] = den; wls[wid] = ls; }
    __syncthreads();
    if (tid == 0) {
        float d = 0.f, L = 0.f;
        #pragma unroll
        for (int w = 0; w < 8; ++w) { d += wden[w]; L += wls[w]; }
        g_cpart[i] = (float)(N_CON - 1 - i) * logf(d) - L;
    }
}

// ---------------- kernel 4: projection A/B via bf16 mma.sync -----------------
// grid (10, 2): mt<8 -> B-part rows mt*64 (W1 cols [768:1536)); mt>=8 -> A-part
// rows (mt-8)*64 of z[:128] (W1 cols [0:768), +b1). ny = N half (128 cols).
#define PJ_STRIDE 136
#define PROJ_SMEM ((64 * PJ_STRIDE + 128 * PJ_STRIDE) * 2)
__global__ __launch_bounds__(256, 2) void proj_mma_kernel(const float* __restrict__ b1) {
    extern __shared__ __nv_bfloat16 psm[];
    __nv_bfloat16* zs = psm;                    // [64][136]
    __nv_bfloat16* ws = psm + 64 * PJ_STRIDE;   // [128][136]
    int mt = blockIdx.x, ny = blockIdx.y;
    int tid = threadIdx.x, lane = tid & 31, wid = tid >> 5;
    bool isA = (mt >= 8);
    int m0 = isA ? (mt - 8) * 64 : mt * 64;     // row into z (A uses rows 0..127)
    int koff = isA ? 0 : D_DIM;
    int n0 = ny * 128;
    int mw = wid & 1, nw = wid >> 1;            // 2 warps in M, 4 in N
    int g = lane >> 2, tg = lane & 3;

    float acc[2][4][4];
    #pragma unroll
    for (int ms = 0; ms < 2; ++ms)
        #pragma unroll
        for (int ns = 0; ns < 4; ++ns)
            #pragma unroll
            for (int q = 0; q < 4; ++q) acc[ms][ns][q] = 0.f;

    for (int ch = 0; ch < 6; ++ch) {
        #pragma unroll
        for (int u = 0; u < 4; ++u) {           // zs: 64 rows x 16 uint4
            int e = tid + u * 256; int r = e >> 4, q = e & 15;
            uint4 v = ((const uint4*)(g_zh + (m0 + r) * D_DIM + ch * 128))[q];
            *(uint4*)(zs + r * PJ_STRIDE + q * 8) = v;
        }
        #pragma unroll
        for (int u = 0; u < 8; ++u) {           // ws: 128 rows x 16 uint4
            int e = tid + u * 256; int r = e >> 4, q = e & 15;
            uint4 v = ((const uint4*)(g_W1h + (n0 + r) * (2 * D_DIM) + koff + ch * 128))[q];
            *(uint4*)(ws + r * PJ_STRIDE + q * 8) = v;
        }
        __syncthreads();
        #pragma unroll
        for (int ks = 0; ks < 8; ++ks) {
            int k0 = ks * 16;
            unsigned a[2][4];
            #pragma unroll
            for (int ms = 0; ms < 2; ++ms) {
                const __nv_bfloat16* base = zs + (mw * 32 + ms * 16 + g) * PJ_STRIDE + k0 + 2 * tg;
                a[ms][0] = *(const unsigned*)(base);
                a[ms][1] = *(const unsigned*)(base + 8 * PJ_STRIDE);
                a[ms][2] = *(const unsigned*)(base + 8);
                a[ms][3] = *(const unsigned*)(base + 8 * PJ_STRIDE + 8);
            }
            unsigned bfr[4][2];
            #pragma unroll
            for (int ns = 0; ns < 4; ++ns) {
                const __nv_bfloat16* bb = ws + (nw * 32 + ns * 8 + g) * PJ_STRIDE + k0 + 2 * tg;
                bfr[ns][0] = *(const unsigned*)(bb);
                bfr[ns][1] = *(const unsigned*)(bb + 8);
            }
            #pragma unroll
            for (int ms = 0; ms < 2; ++ms)
                #pragma unroll
                for (int ns = 0; ns < 4; ++ns)
                    asm volatile(
                        "mma.sync.aligned.m16n8k16.row.col.f32.bf16.bf16.f32 "
                        "{%0,%1,%2,%3}, {%4,%5,%6,%7}, {%8,%9}, {%0,%1,%2,%3};"
                        : "+f"(acc[ms][ns][0]), "+f"(acc[ms][ns][1]),
                          "+f"(acc[ms][ns][2]), "+f"(acc[ms][ns][3])
                        : "r"(a[ms][0]), "r"(a[ms][1]), "r"(a[ms][2]), "r"(a[ms][3]),
                          "r"(bfr[ns][0]), "r"(bfr[ns][1]));
        }
        __syncthreads();
    }
    #pragma unroll
    for (int ms = 0; ms < 2; ++ms)
        #pragma unroll
        for (int ns = 0; ns < 4; ++ns) {
            int row = m0 + mw * 32 + ms * 16 + g;
            int col = n0 + nw * 32 + ns * 8 + 2 * tg;
            if (isA) {
                float b10 = b1[col], b11 = b1[col + 1];
                g_Ah[row * H_DIM + col]           = __float2bfloat16(acc[ms][ns][0] + b10);
                g_Ah[row * H_DIM + col + 1]       = __float2bfloat16(acc[ms][ns][1] + b11);
                g_Ah[(row + 8) * H_DIM + col]     = __float2bfloat16(acc[ms][ns][2] + b10);
                g_Ah[(row + 8) * H_DIM + col + 1] = __float2bfloat16(acc[ms][ns][3] + b11);
            } else {
                g_Bh[row * H_DIM + col]           = __float2bfloat16(acc[ms][ns][0]);
                g_Bh[row * H_DIM + col + 1]       = __float2bfloat16(acc[ms][ns][1]);
                g_Bh[(row + 8) * H_DIM + col]     = __float2bfloat16(acc[ms][ns][2]);
                g_Bh[(row + 8) * H_DIM + col + 1] = __float2bfloat16(acc[ms][ns][3]);
            }
        }
}

// ---------------- kernel 5: pair MLP via bf16 mma.sync (2 CTA/SM) -----------
// Block (c, i, nh): 128 pairs (i, j) with j in [128c, 128c+128), N-half nh.
#define SM_STRIDE 264   // h1: 256 + 8 pad
#define W2_STRIDE 72    // w2 chunk: 64 + 8 pad
#define PAIR2_SMEM (128 * SM_STRIDE * 2 + 2 * 128 * W2_STRIDE * 2)
__global__ __launch_bounds__(256, 2) void pair_mma_kernel(const float* __restrict__ b2,
                                                          const float* __restrict__ W3) {
    extern __shared__ __nv_bfloat16 sm[];
    __nv_bfloat16* h1s = sm;                         // [128][264]
    __nv_bfloat16* w2s = sm + 128 * SM_STRIDE;       // [2][128][72]

    int c = blockIdx.x, i = blockIdx.y, nh = blockIdx.z;
    int tid = threadIdx.x, lane = tid & 31, wid = tid >> 5;
    int j0 = c * 128;

    // ---- build h1 tile: h1[r][k] = relu(Ah[i][k] + Bh[j0+r][k]) ----
    const __nv_bfloat162* Arow = (const __nv_bfloat162*)(g_Ah + i * H_DIM);
    for (int e = tid; e < 128 * 128; e += 256) {
        int r = e >> 7, kp = e & 127;
        __nv_bfloat162 av = Arow[kp];
        __nv_bfloat162 bv = ((const __nv_bfloat162*)(g_Bh + (j0 + r) * H_DIM))[kp];
        float x = fmaxf(__bfloat162float(av.x) + __bfloat162float(bv.x), 0.f);
        float y = fmaxf(__bfloat162float(av.y) + __bfloat162float(bv.y), 0.f);
        *(__nv_bfloat162*)(h1s + r * SM_STRIDE + 2 * kp) = __floats2bfloat162_rn(x, y);
    }
    // ---- stage W2 K-chunk 0 ----
    {
        #pragma unroll
        for (int u = 0; u < 4; ++u) {
            int e = tid + u * 256; int r = e >> 3, q = e & 7;
            uint4 v = ((const uint4*)(g_W2h + (nh * 128 + r) * H_DIM))[q];
            *(uint4*)(w2s + r * W2_STRIDE + q * 8) = v;
        }
    }
    __syncthreads();

    int mw = wid & 3, nw = wid >> 2;   // 4 warps in M (32 rows), 2 in N (64 cols)
    int g = lane >> 2, tg = lane & 3;

    float acc[2][8][4];
    #pragma unroll
    for (int ms = 0; ms < 2; ++ms)
        #pragma unroll
        for (int ns = 0; ns < 8; ++ns)
            #pragma unroll
            for (int q = 0; q < 4; ++q) acc[ms][ns][q] = 0.f;

    for (int ch = 0; ch < 4; ++ch) {
        int buf = ch & 1;
        if (ch < 3) {
            int nb = buf ^ 1;
            #pragma unroll
            for (int u = 0; u < 4; ++u) {
                int e = tid + u * 256; int r = e >> 3, q = e & 7;
                uint4 v = ((const uint4*)(g_W2h + (nh * 128 + r) * H_DIM + (ch + 1) * 64))[q];
                *(uint4*)(w2s + nb * 128 * W2_STRIDE + r * W2_STRIDE + q * 8) = v;
            }
        }
        #pragma unroll
        for (int ksl = 0; ksl < 4; ++ksl) {
            int k0 = ch * 64 + ksl * 16;   // global k for h1
            int k0l = ksl * 16;            // local k in w2 chunk
            unsigned a[2][4];
            #pragma unroll
            for (int ms = 0; ms < 2; ++ms) {
                const __nv_bfloat16* base0 = h1s + (mw * 32 + ms * 16 + g) * SM_STRIDE + k0 + 2 * tg;
                a[ms][0] = *(const unsigned*)(base0);
                a[ms][1] = *(const unsigned*)(base0 + 8 * SM_STRIDE);
                a[ms][2] = *(const unsigned*)(base0 + 8);
                a[ms][3] = *(const unsigned*)(base0 + 8 * SM_STRIDE + 8);
            }
            unsigned bfr[8][2];
            #pragma unroll
            for (int ns = 0; ns < 8; ++ns) {
                const __nv_bfloat16* bb = w2s + buf * 128 * W2_STRIDE
                                        + (nw * 64 + ns * 8 + g) * W2_STRIDE + k0l + 2 * tg;
                bfr[ns][0] = *(const unsigned*)(bb);
                bfr[ns][1] = *(const unsigned*)(bb + 8);
            }
            #pragma unroll
            for (int ms = 0; ms < 2; ++ms)
                #pragma unroll
                for (int ns = 0; ns < 8; ++ns)
                    asm volatile(
                        "mma.sync.aligned.m16n8k16.row.col.f32.bf16.bf16.f32 "
                        "{%0,%1,%2,%3}, {%4,%5,%6,%7}, {%8,%9}, {%0,%1,%2,%3};"
                        : "+f"(acc[ms][ns][0]), "+f"(acc[ms][ns][1]),
                          "+f"(acc[ms][ns][2]), "+f"(acc[ms][ns][3])
                        : "r"(a[ms][0]), "r"(a[ms][1]), "r"(a[ms][2]), "r"(a[ms][3]),
                          "r"(bfr[ns][0]), "r"(bfr[ns][1]));
        }
        __syncthreads();
    }

    // ---- epilogue: relu(h2 + b2) dot W3 over this block's n, per pair-row --
    #pragma unroll
    for (int ms = 0; ms < 2; ++ms) {
        float rs0 = 0.f, rs1 = 0.f;
        #pragma unroll
        for (int ns = 0; ns < 8; ++ns) {
            int n0 = nh * 128 + nw * 64 + ns * 8 + 2 * tg;
            float b20 = __ldg(b2 + n0), b21 = __ldg(b2 + n0 + 1);
            float w30 = __ldg(W3 + n0), w31 = __ldg(W3 + n0 + 1);
            rs0 += fmaxf(acc[ms][ns][0] + b20, 0.f) * w30
                 + fmaxf(acc[ms][ns][1] + b21, 0.f) * w31;
            rs1 += fmaxf(acc[ms][ns][2] + b20, 0.f) * w30
                 + fmaxf(acc[ms][ns][3] + b21, 0.f) * w31;
        }
        rs0 += __shfl_xor_sync(0xffffffffu, rs0, 1);
        rs0 += __shfl_xor_sync(0xffffffffu, rs0, 2);
        rs1 += __shfl_xor_sync(0xffffffffu, rs1, 1);
        rs1 += __shfl_xor_sync(0xffffffffu, rs1, 2);
        if (tg == 0) {
            int r = mw * 32 + ms * 16 + g;
            g_lp[nh][i][j0 + r]     = rs0;
            g_lp[nh][i][j0 + r + 8] = rs1;
        }
    }
}

// ---------------- kernel 6: bce over valid pairs ----------------------------
__global__ __launch_bounds__(256) void bce_kernel(const float* __restrict__ b3) {
    __shared__ float red[8];
    int i = blockIdx.x, tid = threadIdx.x, lane = tid & 31, wid = tid >> 5;
    float b3v = b3[0];
    float s = 0.f;
    for (int j = i + 1 + tid; j < B_ROWS; j += 256) {
        float l = b3v + g_lp[0][i][j] + g_lp[1][i][j];
        float y = (j < M_POS) ? 1.f : 0.f;
        s += fmaxf(l, 0.f) - l * y + log1pf(expf(-fabsf(l)));
    }
    #pragma unroll
    for (int o = 16; o; o >>= 1) s += __shfl_xor_sync(0xffffffffu, s, o);
    if (lane == 0) red[wid] = s;
    __syncthreads();
    if (tid == 0) {
        float t = 0.f;
        #pragma unroll
        for (int w = 0; w < 8; ++w) t += red[w];
        g_epart[i] = t;
    }
}

// ---------------- kernel 7: final reduction ---------------------------------
__global__ __launch_bounds__(128) void final_kernel(float* __restrict__ out) {
    __shared__ float red[128];
    int tid = threadIdx.x;
    red[tid] = g_epart[tid];
    __syncthreads();
    for (int s = 64; s; s >>= 1) {
        if (tid < s) red[tid] += red[tid + s];
        __syncthreads();
    }
    float esum = red[0];
    __syncthreads();
    red[tid] = g_cpart[tid];
    __syncthreads();
    for (int s = 64; s; s >>= 1) {
        if (tid < s) red[tid] += red[tid + s];
        __syncthreads();
    }
    if (tid == 0) {
        float closs = -1.984375f * red[0];        // -2*(n-1)/n * closs_sum
        out[0] = closs + esum * (1.0f / NPAIRS);  // + mean BCE
    }
}

// ---------------- launch -----------------------------------------------------
extern "C" void kernel_launch(void* const* d_in, const int* in_sizes, int n_in,
                              void* d_out, int out_size) {
    const float* emb = (const float*)d_in[0];
    const float* W1  = (const float*)d_in[1];
    const float* b1  = (const float*)d_in[2];
    const float* W2  = (const float*)d_in[3];
    const float* b2  = (const float*)d_in[4];
    const float* W3  = (const float*)d_in[5];
    const float* b3  = (const float*)d_in[6];
    float* out = (float*)d_out;

    cudaFuncSetAttribute(pair_mma_kernel, cudaFuncAttributeMaxDynamicSharedMemorySize, PAIR2_SMEM);
    cudaFuncSetAttribute(proj_mma_kernel, cudaFuncAttributeMaxDynamicSharedMemorySize, PROJ_SMEM);

    prep_kernel<<<1792, 256>>>(W1, W2);
    normalize_kernel<<<B_ROWS, 256>>>(emb);
    contrastive_kernel<<<N_CON, 256>>>();
    proj_mma_kernel<<<dim3(10, 2), 256, PROJ_SMEM>>>(b1);
    pair_mma_kernel<<<dim3(4, N_CON, 2), 256, PAIR2_SMEM>>>(b2, W3);
    bce_kernel<<<N_CON, 256>>>(b3);
    final_kernel<<<1, 128>>>(out);
}

// round 8
// speedup vs baseline: 1.8595x; 1.8595x over previous
#include <cuda_runtime.h>
#include <cuda_bf16.h>
#include <math.h>

// Shapes (fixed by the problem)
//  emb_in [512,768], W1 [256,1536], b1[256], W2 [256,256], b2[256], W3[1,256], b3[1]
#define B_ROWS 512
#define D_DIM  768
#define H_DIM  256
#define N_CON  128      // n = B/4
#define M_POS  256      // m = B/2
#define NPAIRS 57280.0f

// ---------------- device scratch (statically allocated: no cudaMalloc) -----
__device__ __nv_bfloat16 g_zh[B_ROWS * D_DIM];     // normalized rows (bf16)
__device__ __nv_bfloat16 g_W1h[H_DIM * 2 * D_DIM]; // W1 bf16, natural [n][1536]
__device__ __nv_bfloat16 g_W2h[H_DIM * H_DIM];     // W2 bf16, natural [n][k]
__device__ __nv_bfloat16 g_Ah[N_CON * H_DIM];      // (z[:128] @ W1a.T + b1) bf16
__device__ __nv_bfloat16 g_Bh[B_ROWS * H_DIM];     // (z @ W1b.T) bf16
__device__ float g_denp[4][N_CON];                 // contrastive denom partials (per j-tile)
__device__ float g_lsp[4][N_CON];                  // contrastive logit-sum partials
__device__ float g_lp[2][N_CON][B_ROWS];           // pair logit partials per N-half
__device__ float g_epart[N_CON];                   // bce partials per i

// ---------------- kernel 1: fused L2-normalize + weight bf16 convert --------
__global__ __launch_bounds__(256) void prep_norm_kernel(const float* __restrict__ emb,
                                                        const float* __restrict__ W1,
                                                        const float* __restrict__ W2) {
    int b = blockIdx.x, tid = threadIdx.x;
    if (b < B_ROWS) {
        int lane = tid & 31, wid = tid >> 5;
        const float* r = emb + b * D_DIM;
        float s = 0.f;
        for (int k = tid; k < D_DIM; k += 256) { float v = r[k]; s += v * v; }
        #pragma unroll
        for (int o = 16; o; o >>= 1) s += __shfl_xor_sync(0xffffffffu, s, o);
        __shared__ float red[8];
        __shared__ float rn;
        if (lane == 0) red[wid] = s;
        __syncthreads();
        if (tid == 0) {
            float t = 0.f;
            #pragma unroll
            for (int w = 0; w < 8; ++w) t += red[w];
            rn = 1.0f / fmaxf(sqrtf(t), 1e-12f);
        }
        __syncthreads();
        float rnv = rn;
        for (int k = tid; k < D_DIM; k += 256)
            g_zh[b * D_DIM + k] = __float2bfloat16(r[k] * rnv);
    } else {
        // convert W1 (393216 elems) then W2 (65536 elems), flat, float4-granular
        int idx = (b - B_ROWS) * 1024 + tid * 4;   // 448 blocks x 1024 elems
        float4 v;
        __nv_bfloat16* dst;
        if (idx < 393216) { v = *(const float4*)(W1 + idx); dst = g_W1h + idx; }
        else              { v = *(const float4*)(W2 + (idx - 393216)); dst = g_W2h + (idx - 393216); }
        *(__nv_bfloat162*)(dst)     = __floats2bfloat162_rn(v.x, v.y);
        *(__nv_bfloat162*)(dst + 2) = __floats2bfloat162_rn(v.z, v.w);
    }
}

// ---------------- kernel 2: unified bf16 mma GEMM (proj + contrastive S) ----
// 28 blocks, each a 64M x 128N x 768K GEMM tile.
//  b in [0,20): proj. mt=b>>1, ny=b&1.
//    mt<8 : Bh rows mt*64    = z rows   @ W1 cols [768:1536)
//    mt>=8: Ah rows (mt-8)*64 (+b1)     @ W1 cols [0:768)
//  b in [20,28): S-tile. e=b-20: it=e>>2 (i-tile of 64), jt=e&3 (j-tile of 128).
//    epilogue: denp/lsp partial reductions over this block's 128 j's.
#define MID_STRIDE 136
#define MID_SMEM ((64 + 128) * MID_STRIDE * 2 + 2 * 256 * 4)
__global__ __launch_bounds__(256, 2) void mid_kernel(const float* __restrict__ b1) {
    extern __shared__ __nv_bfloat16 msm[];
    __nv_bfloat16* zs = msm;                      // [64][136]
    __nv_bfloat16* ws = msm + 64 * MID_STRIDE;    // [128][136]
    float* denred = (float*)(msm + 192 * MID_STRIDE);  // [4][64]
    float* lsred  = denred + 256;                      // [4][64]

    int b = blockIdx.x;
    int tid = threadIdx.x, lane = tid & 31, wid = tid >> 5;
    bool isS = (b >= 20);
    bool isA = false;
    int m0, koff, n0, bstride;
    const __nv_bfloat16* bsrc;
    if (!isS) {
        int mt = b >> 1, ny = b & 1;
        isA = (mt >= 8);
        m0 = isA ? (mt - 8) * 64 : mt * 64;
        koff = isA ? 0 : D_DIM;
        bsrc = g_W1h; bstride = 2 * D_DIM;
        n0 = ny * 128;
    } else {
        int e = b - 20;
        m0 = (e >> 2) * 64;
        koff = 0;
        bsrc = g_zh; bstride = D_DIM;
        n0 = (e & 3) * 128;
    }
    int mw = wid & 1, nw = wid >> 1;   // 2 warps in M, 4 in N
    int g = lane >> 2, tg = lane & 3;

    float acc[2][4][4];
    #pragma unroll
    for (int ms = 0; ms < 2; ++ms)
        #pragma unroll
        for (int ns = 0; ns < 4; ++ns)
            #pragma unroll
            for (int q = 0; q < 4; ++q) acc[ms][ns][q] = 0.f;

    for (int ch = 0; ch < 6; ++ch) {
        #pragma unroll
        for (int u = 0; u < 4; ++u) {           // zs: 64 rows x 16 uint4
            int e = tid + u * 256; int r = e >> 4, q = e & 15;
            uint4 v = ((const uint4*)(g_zh + (m0 + r) * D_DIM + ch * 128))[q];
            *(uint4*)(zs + r * MID_STRIDE + q * 8) = v;
        }
        #pragma unroll
        for (int u = 0; u < 8; ++u) {           // ws: 128 rows x 16 uint4
            int e = tid + u * 256; int r = e >> 4, q = e & 15;
            uint4 v = ((const uint4*)(bsrc + (n0 + r) * bstride + koff + ch * 128))[q];
            *(uint4*)(ws + r * MID_STRIDE + q * 8) = v;
        }
        __syncthreads();
        #pragma unroll
        for (int ks = 0; ks < 8; ++ks) {
            int k0 = ks * 16;
            unsigned a[2][4];
            #pragma unroll
            for (int ms = 0; ms < 2; ++ms) {
                const __nv_bfloat16* base = zs + (mw * 32 + ms * 16 + g) * MID_STRIDE + k0 + 2 * tg;
                a[ms][0] = *(const unsigned*)(base);
                a[ms][1] = *(const unsigned*)(base + 8 * MID_STRIDE);
                a[ms][2] = *(const unsigned*)(base + 8);
                a[ms][3] = *(const unsigned*)(base + 8 * MID_STRIDE + 8);
            }
            unsigned bfr[4][2];
            #pragma unroll
            for (int ns = 0; ns < 4; ++ns) {
                const __nv_bfloat16* bb = ws + (nw * 32 + ns * 8 + g) * MID_STRIDE + k0 + 2 * tg;
                bfr[ns][0] = *(const unsigned*)(bb);
                bfr[ns][1] = *(const unsigned*)(bb + 8);
            }
            #pragma unroll
            for (int ms = 0; ms < 2; ++ms)
                #pragma unroll
                for (int ns = 0; ns < 4; ++ns)
                    asm volatile(
                        "mma.sync.aligned.m16n8k16.row.col.f32.bf16.bf16.f32 "
                        "{%0,%1,%2,%3}, {%4,%5,%6,%7}, {%8,%9}, {%0,%1,%2,%3};"
                        : "+f"(acc[ms][ns][0]), "+f"(acc[ms][ns][1]),
                          "+f"(acc[ms][ns][2]), "+f"(acc[ms][ns][3])
                        : "r"(a[ms][0]), "r"(a[ms][1]), "r"(a[ms][2]), "r"(a[ms][3]),
                          "r"(bfr[ns][0]), "r"(bfr[ns][1]));
        }
        __syncthreads();
    }

    if (!isS) {
        // ---- proj epilogue: write Ah (+b1) / Bh ----
        #pragma unroll
        for (int ms = 0; ms < 2; ++ms)
            #pragma unroll
            for (int ns = 0; ns < 4; ++ns) {
                int row = m0 + mw * 32 + ms * 16 + g;
                int col = n0 + nw * 32 + ns * 8 + 2 * tg;
                if (isA) {
                    float b10 = b1[col], b11 = b1[col + 1];
                    g_Ah[row * H_DIM + col]           = __float2bfloat16(acc[ms][ns][0] + b10);
                    g_Ah[row * H_DIM + col + 1]       = __float2bfloat16(acc[ms][ns][1] + b11);
                    g_Ah[(row + 8) * H_DIM + col]     = __float2bfloat16(acc[ms][ns][2] + b10);
                    g_Ah[(row + 8) * H_DIM + col + 1] = __float2bfloat16(acc[ms][ns][3] + b11);
                } else {
                    g_Bh[row * H_DIM + col]           = __float2bfloat16(acc[ms][ns][0]);
                    g_Bh[row * H_DIM + col + 1]       = __float2bfloat16(acc[ms][ns][1]);
                    g_Bh[(row + 8) * H_DIM + col]     = __float2bfloat16(acc[ms][ns][2]);
                    g_Bh[(row + 8) * H_DIM + col + 1] = __float2bfloat16(acc[ms][ns][3]);
                }
            }
    } else {
        // ---- S epilogue: per-i partial denom / pair-logit-sum over 128 j's --
        #pragma unroll
        for (int ms = 0; ms < 2; ++ms) {
            float d0 = 0.f, l0 = 0.f, d1 = 0.f, l1 = 0.f;
            int row0 = mw * 32 + ms * 16 + g;     // local rows row0, row0+8
            int ig0 = m0 + row0;
            #pragma unroll
            for (int ns = 0; ns < 4; ++ns)
                #pragma unroll
                for (int q = 0; q < 4; ++q) {
                    int jg = n0 + nw * 32 + ns * 8 + 2 * tg + (q & 1);
                    int ig = ig0 + ((q >= 2) ? 8 : 0);
                    float v = 2.0f * acc[ms][ns][q];
                    float e = (jg != ig) ? expf(v) : 0.f;
                    float lv = (jg > ig && jg < N_CON) ? v : 0.f;
                    if (q < 2) { d0 += e; l0 += lv; } else { d1 += e; l1 += lv; }
                }
            d0 += __shfl_xor_sync(0xffffffffu, d0, 1); d0 += __shfl_xor_sync(0xffffffffu, d0, 2);
            l0 += __shfl_xor_sync(0xffffffffu, l0, 1); l0 += __shfl_xor_sync(0xffffffffu, l0, 2);
            d1 += __shfl_xor_sync(0xffffffffu, d1, 1); d1 += __shfl_xor_sync(0xffffffffu, d1, 2);
            l1 += __shfl_xor_sync(0xffffffffu, l1, 1); l1 += __shfl_xor_sync(0xffffffffu, l1, 2);
            if (tg == 0) {
                denred[nw * 64 + row0]     = d0;  lsred[nw * 64 + row0]     = l0;
                denred[nw * 64 + row0 + 8] = d1;  lsred[nw * 64 + row0 + 8] = l1;
            }
        }
        __syncthreads();
        if (tid < 64) {
            int jt = (b - 20) & 3;
            float den = 0.f, ls = 0.f;
            #pragma unroll
            for (int w = 0; w < 4; ++w) { den += denred[w * 64 + tid]; ls += lsred[w * 64 + tid]; }
            g_denp[jt][m0 + tid] = den;
            g_lsp[jt][m0 + tid]  = ls;
        }
    }
}

// ---------------- kernel 3: pair MLP via bf16 mma.sync (round-6 1-CTA) ------
// Block (c, i, nh): 128 pairs (i, j) with j in [128c, 128c+128), N-half nh.
#define SM_STRIDE 264   // 256 + 8 bf16 pad -> conflict-free fragment LDS
#define PAIR2_SMEM (2 * 128 * SM_STRIDE * 2)
__global__ __launch_bounds__(256, 1) void pair_mma_kernel(const float* __restrict__ b2,
                                                          const float* __restrict__ W3) {
    extern __shared__ __nv_bfloat16 sm[];
    __nv_bfloat16* h1s = sm;                         // [128][264]
    __nv_bfloat16* w2s = sm + 128 * SM_STRIDE;       // [128][264]

    int c = blockIdx.x, i = blockIdx.y, nh = blockIdx.z;
    int tid = threadIdx.x, lane = tid & 31, wid = tid >> 5;
    int j0 = c * 128;

    // ---- build h1 tile: h1[r][k] = relu(Ah[i][k] + Bh[j0+r][k]) ----
    const __nv_bfloat162* Arow = (const __nv_bfloat162*)(g_Ah + i * H_DIM);
    for (int e = tid; e < 128 * 128; e += 256) {
        int r = e >> 7, kp = e & 127;
        __nv_bfloat162 av = Arow[kp];
        __nv_bfloat162 bv = ((const __nv_bfloat162*)(g_Bh + (j0 + r) * H_DIM))[kp];
        float x = fmaxf(__bfloat162float(av.x) + __bfloat162float(bv.x), 0.f);
        float y = fmaxf(__bfloat162float(av.y) + __bfloat162float(bv.y), 0.f);
        *(__nv_bfloat162*)(h1s + r * SM_STRIDE + 2 * kp) = __floats2bfloat162_rn(x, y);
    }
    // ---- stage W2 half: rows n = nh*128 + r ----
    for (int e = tid; e < 128 * 32; e += 256) {
        int r = e >> 5, q = e & 31;
        uint4 v = ((const uint4*)(g_W2h + (nh * 128 + r) * H_DIM))[q];
        *(uint4*)(w2s + r * SM_STRIDE + q * 8) = v;
    }
    __syncthreads();

    int mw = wid & 3, nw = wid >> 2;   // 4 warps in M, 2 in N
    int g = lane >> 2, tg = lane & 3;

    float acc[2][8][4];
    #pragma unroll
    for (int ms = 0; ms < 2; ++ms)
        #pragma unroll
        for (int ns = 0; ns < 8; ++ns)
            #pragma unroll
            for (int q = 0; q < 4; ++q) acc[ms][ns][q] = 0.f;

    #pragma unroll 2
    for (int ks = 0; ks < 16; ++ks) {
        int k0 = ks * 16;
        unsigned a[2][4];
        #pragma unroll
        for (int ms = 0; ms < 2; ++ms) {
            const __nv_bfloat16* base0 = h1s + (mw * 32 + ms * 16 + g) * SM_STRIDE + k0 + 2 * tg;
            a[ms][0] = *(const unsigned*)(base0);
            a[ms][1] = *(const unsigned*)(base0 + 8 * SM_STRIDE);
            a[ms][2] = *(const unsigned*)(base0 + 8);
            a[ms][3] = *(const unsigned*)(base0 + 8 * SM_STRIDE + 8);
        }
        unsigned bfr[8][2];
        #pragma unroll
        for (int ns = 0; ns < 8; ++ns) {
            const __nv_bfloat16* bb = w2s + (nw * 64 + ns * 8 + g) * SM_STRIDE + k0 + 2 * tg;
            bfr[ns][0] = *(const unsigned*)(bb);
            bfr[ns][1] = *(const unsigned*)(bb + 8);
        }
        #pragma unroll
        for (int ms = 0; ms < 2; ++ms)
            #pragma unroll
            for (int ns = 0; ns < 8; ++ns)
                asm volatile(
                    "mma.sync.aligned.m16n8k16.row.col.f32.bf16.bf16.f32 "
                    "{%0,%1,%2,%3}, {%4,%5,%6,%7}, {%8,%9}, {%0,%1,%2,%3};"
                    : "+f"(acc[ms][ns][0]), "+f"(acc[ms][ns][1]),
                      "+f"(acc[ms][ns][2]), "+f"(acc[ms][ns][3])
                    : "r"(a[ms][0]), "r"(a[ms][1]), "r"(a[ms][2]), "r"(a[ms][3]),
                      "r"(bfr[ns][0]), "r"(bfr[ns][1]));
    }

    // ---- epilogue: relu(h2 + b2) dot W3 over this block's n, per pair-row --
    #pragma unroll
    for (int ms = 0; ms < 2; ++ms) {
        float rs0 = 0.f, rs1 = 0.f;
        #pragma unroll
        for (int ns = 0; ns < 8; ++ns) {
            int n0 = nh * 128 + nw * 64 + ns * 8 + 2 * tg;
            float b20 = __ldg(b2 + n0), b21 = __ldg(b2 + n0 + 1);
            float w30 = __ldg(W3 + n0), w31 = __ldg(W3 + n0 + 1);
            rs0 += fmaxf(acc[ms][ns][0] + b20, 0.f) * w30
                 + fmaxf(acc[ms][ns][1] + b21, 0.f) * w31;
            rs1 += fmaxf(acc[ms][ns][2] + b20, 0.f) * w30
                 + fmaxf(acc[ms][ns][3] + b21, 0.f) * w31;
        }
        rs0 += __shfl_xor_sync(0xffffffffu, rs0, 1);
        rs0 += __shfl_xor_sync(0xffffffffu, rs0, 2);
        rs1 += __shfl_xor_sync(0xffffffffu, rs1, 1);
        rs1 += __shfl_xor_sync(0xffffffffu, rs1, 2);
        if (tg == 0) {
            int r = mw * 32 + ms * 16 + g;
            g_lp[nh][i][j0 + r]     = rs0;
            g_lp[nh][i][j0 + r + 8] = rs1;
        }
    }
}

// ---------------- kernel 4: bce over valid pairs ----------------------------
__global__ __launch_bounds__(256) void bce_kernel(const float* __restrict__ b3) {
    __shared__ float red[8];
    int i = blockIdx.x, tid = threadIdx.x, lane = tid & 31, wid = tid >> 5;
    float b3v = b3[0];
    float s = 0.f;
    for (int j = i + 1 + tid; j < B_ROWS; j += 256) {
        float l = b3v + g_lp[0][i][j] + g_lp[1][i][j];
        float y = (j < M_POS) ? 1.f : 0.f;
        s += fmaxf(l, 0.f) - l * y + log1pf(expf(-fabsf(l)));
    }
    #pragma unroll
    for (int o = 16; o; o >>= 1) s += __shfl_xor_sync(0xffffffffu, s, o);
    if (lane == 0) red[wid] = s;
    __syncthreads();
    if (tid == 0) {
        float t = 0.f;
        #pragma unroll
        for (int w = 0; w < 8; ++w) t += red[w];
        g_epart[i] = t;
    }
}

// ---------------- kernel 5: final reduction (closs from partials + eloss) ----
__global__ __launch_bounds__(128) void final_kernel(float* __restrict__ out) {
    __shared__ float red[128];
    int tid = threadIdx.x;   // one thread per i
    float den = 0.f, ls = 0.f;
    #pragma unroll
    for (int t = 0; t < 4; ++t) { den += g_denp[t][tid]; ls += g_lsp[t][tid]; }
    float cpart = (float)(N_CON - 1 - tid) * logf(den) - ls;
    red[tid] = cpart;
    __syncthreads();
    for (int s = 64; s; s >>= 1) {
        if (tid < s) red[tid] += red[tid + s];
        __syncthreads();
    }
    float csum = red[0];
    __syncthreads();
    red[tid] = g_epart[tid];
    __syncthreads();
    for (int s = 64; s; s >>= 1) {
        if (tid < s) red[tid] += red[tid + s];
        __syncthreads();
    }
    if (tid == 0) {
        float closs = -1.984375f * csum;          // -2*(n-1)/n * closs_sum
        out[0] = closs + red[0] * (1.0f / NPAIRS);
    }
}

// ---------------- launch -----------------------------------------------------
extern "C" void kernel_launch(void* const* d_in, const int* in_sizes, int n_in,
                              void* d_out, int out_size) {
    const float* emb = (const float*)d_in[0];
    const float* W1  = (const float*)d_in[1];
    const float* b1  = (const float*)d_in[2];
    const float* b2  = (const float*)d_in[4];
    const float* W2  = (const float*)d_in[3];
    const float* W3  = (const float*)d_in[5];
    const float* b3  = (const float*)d_in[6];
    float* out = (float*)d_out;

    cudaFuncSetAttribute(mid_kernel, cudaFuncAttributeMaxDynamicSharedMemorySize, MID_SMEM);
    cudaFuncSetAttribute(pair_mma_kernel, cudaFuncAttributeMaxDynamicSharedMemorySize, PAIR2_SMEM);

    prep_norm_kernel<<<B_ROWS + 448, 256>>>(emb, W1, W2);
    mid_kernel<<<28, 256, MID_SMEM>>>(b1);
    pair_mma_kernel<<<dim3(4, N_CON, 2), 256, PAIR2_SMEM>>>(b2, W3);
    bce_kernel<<<N_CON, 256>>>(b3);
    final_kernel<<<1, 128>>>(out);
}

// round 9
// speedup vs baseline: 2.4368x; 1.3105x over previous
#include <cuda_runtime.h>
#include <cuda_bf16.h>
#include <math.h>

// Shapes (fixed by the problem)
//  emb_in [512,768], W1 [256,1536], b1[256], W2 [256,256], b2[256], W3[1,256], b3[1]
#define B_ROWS 512
#define D_DIM  768
#define H_DIM  256
#define N_CON  128      // n = B/4
#define M_POS  256      // m = B/2
#define NPAIRS 57280.0f

// ---------------- device scratch (statically allocated: no cudaMalloc) -----
__device__ __nv_bfloat16 g_zh[B_ROWS * D_DIM];     // normalized rows (bf16)
__device__ __nv_bfloat16 g_W1h[H_DIM * 2 * D_DIM]; // W1 bf16, natural [n][1536]
__device__ __nv_bfloat16 g_W2h[H_DIM * H_DIM];     // W2 bf16, natural [n][k]
__device__ __nv_bfloat16 g_Ah[N_CON * H_DIM];      // (z[:128] @ W1a.T + b1) bf16
__device__ __nv_bfloat16 g_Bh[B_ROWS * H_DIM];     // (z @ W1b.T) bf16
__device__ float g_denp[4][N_CON];                 // contrastive denom partials (per j-tile)
__device__ float g_lsp[4][N_CON];                  // contrastive logit-sum partials
__device__ float g_eblk[4 * N_CON];                // bce partials per (i, j-chunk) block
__device__ float g_out_unused;

// ---------------- kernel 1: fused L2-normalize + weight bf16 convert --------
__global__ __launch_bounds__(256) void prep_norm_kernel(const float* __restrict__ emb,
                                                        const float* __restrict__ W1,
                                                        const float* __restrict__ W2) {
    int b = blockIdx.x, tid = threadIdx.x;
    if (b < B_ROWS) {
        int lane = tid & 31, wid = tid >> 5;
        const float* r = emb + b * D_DIM;
        float s = 0.f;
        for (int k = tid; k < D_DIM; k += 256) { float v = r[k]; s += v * v; }
        #pragma unroll
        for (int o = 16; o; o >>= 1) s += __shfl_xor_sync(0xffffffffu, s, o);
        __shared__ float red[8];
        __shared__ float rn;
        if (lane == 0) red[wid] = s;
        __syncthreads();
        if (tid == 0) {
            float t = 0.f;
            #pragma unroll
            for (int w = 0; w < 8; ++w) t += red[w];
            rn = 1.0f / fmaxf(sqrtf(t), 1e-12f);
        }
        __syncthreads();
        float rnv = rn;
        for (int k = tid; k < D_DIM; k += 256)
            g_zh[b * D_DIM + k] = __float2bfloat16(r[k] * rnv);
    } else {
        // convert W1 (393216 elems) then W2 (65536 elems), flat, float4-granular
        int idx = (b - B_ROWS) * 1024 + tid * 4;   // 448 blocks x 1024 elems
        float4 v;
        __nv_bfloat16* dst;
        if (idx < 393216) { v = *(const float4*)(W1 + idx); dst = g_W1h + idx; }
        else              { v = *(const float4*)(W2 + (idx - 393216)); dst = g_W2h + (idx - 393216); }
        *(__nv_bfloat162*)(dst)     = __floats2bfloat162_rn(v.x, v.y);
        *(__nv_bfloat162*)(dst + 2) = __floats2bfloat162_rn(v.z, v.w);
    }
}

// ---------------- kernel 2: unified bf16 mma GEMM (proj + contrastive S) ----
// 28 blocks, each a 64M x 128N x 768K GEMM tile.
//  b in [0,20): proj. mt=b>>1, ny=b&1.
//    mt<8 : Bh rows mt*64    = z rows   @ W1 cols [768:1536)
//    mt>=8: Ah rows (mt-8)*64 (+b1)     @ W1 cols [0:768)
//  b in [20,28): S-tile. e=b-20: it=e>>2 (i-tile of 64), jt=e&3 (j-tile of 128).
#define MID_STRIDE 136
#define MID_SMEM ((64 + 128) * MID_STRIDE * 2 + 2 * 256 * 4)
__global__ __launch_bounds__(256, 2) void mid_kernel(const float* __restrict__ b1) {
    extern __shared__ __nv_bfloat16 msm[];
    __nv_bfloat16* zs = msm;                      // [64][136]
    __nv_bfloat16* ws = msm + 64 * MID_STRIDE;    // [128][136]
    float* denred = (float*)(msm + 192 * MID_STRIDE);  // [4][64]
    float* lsred  = denred + 256;                      // [4][64]

    int b = blockIdx.x;
    int tid = threadIdx.x, lane = tid & 31, wid = tid >> 5;
    bool isS = (b >= 20);
    bool isA = false;
    int m0, koff, n0, bstride;
    const __nv_bfloat16* bsrc;
    if (!isS) {
        int mt = b >> 1, ny = b & 1;
        isA = (mt >= 8);
        m0 = isA ? (mt - 8) * 64 : mt * 64;
        koff = isA ? 0 : D_DIM;
        bsrc = g_W1h; bstride = 2 * D_DIM;
        n0 = ny * 128;
    } else {
        int e = b - 20;
        m0 = (e >> 2) * 64;
        koff = 0;
        bsrc = g_zh; bstride = D_DIM;
        n0 = (e & 3) * 128;
    }
    int mw = wid & 1, nw = wid >> 1;   // 2 warps in M, 4 in N
    int g = lane >> 2, tg = lane & 3;

    float acc[2][4][4];
    #pragma unroll
    for (int ms = 0; ms < 2; ++ms)
        #pragma unroll
        for (int ns = 0; ns < 4; ++ns)
            #pragma unroll
            for (int q = 0; q < 4; ++q) acc[ms][ns][q] = 0.f;

    for (int ch = 0; ch < 6; ++ch) {
        #pragma unroll
        for (int u = 0; u < 4; ++u) {           // zs: 64 rows x 16 uint4
            int e = tid + u * 256; int r = e >> 4, q = e & 15;
            uint4 v = ((const uint4*)(g_zh + (m0 + r) * D_DIM + ch * 128))[q];
            *(uint4*)(zs + r * MID_STRIDE + q * 8) = v;
        }
        #pragma unroll
        for (int u = 0; u < 8; ++u) {           // ws: 128 rows x 16 uint4
            int e = tid + u * 256; int r = e >> 4, q = e & 15;
            uint4 v = ((const uint4*)(bsrc + (n0 + r) * bstride + koff + ch * 128))[q];
            *(uint4*)(ws + r * MID_STRIDE + q * 8) = v;
        }
        __syncthreads();
        #pragma unroll
        for (int ks = 0; ks < 8; ++ks) {
            int k0 = ks * 16;
            unsigned a[2][4];
            #pragma unroll
            for (int ms = 0; ms < 2; ++ms) {
                const __nv_bfloat16* base = zs + (mw * 32 + ms * 16 + g) * MID_STRIDE + k0 + 2 * tg;
                a[ms][0] = *(const unsigned*)(base);
                a[ms][1] = *(const unsigned*)(base + 8 * MID_STRIDE);
                a[ms][2] = *(const unsigned*)(base + 8);
                a[ms][3] = *(const unsigned*)(base + 8 * MID_STRIDE + 8);
            }
            unsigned bfr[4][2];
            #pragma unroll
            for (int ns = 0; ns < 4; ++ns) {
                const __nv_bfloat16* bb = ws + (nw * 32 + ns * 8 + g) * MID_STRIDE + k0 + 2 * tg;
                bfr[ns][0] = *(const unsigned*)(bb);
                bfr[ns][1] = *(const unsigned*)(bb + 8);
            }
            #pragma unroll
            for (int ms = 0; ms < 2; ++ms)
                #pragma unroll
                for (int ns = 0; ns < 4; ++ns)
                    asm volatile(
                        "mma.sync.aligned.m16n8k16.row.col.f32.bf16.bf16.f32 "
                        "{%0,%1,%2,%3}, {%4,%5,%6,%7}, {%8,%9}, {%0,%1,%2,%3};"
                        : "+f"(acc[ms][ns][0]), "+f"(acc[ms][ns][1]),
                          "+f"(acc[ms][ns][2]), "+f"(acc[ms][ns][3])
                        : "r"(a[ms][0]), "r"(a[ms][1]), "r"(a[ms][2]), "r"(a[ms][3]),
                          "r"(bfr[ns][0]), "r"(bfr[ns][1]));
        }
        __syncthreads();
    }

    if (!isS) {
        #pragma unroll
        for (int ms = 0; ms < 2; ++ms)
            #pragma unroll
            for (int ns = 0; ns < 4; ++ns) {
                int row = m0 + mw * 32 + ms * 16 + g;
                int col = n0 + nw * 32 + ns * 8 + 2 * tg;
                if (isA) {
                    float b10 = b1[col], b11 = b1[col + 1];
                    g_Ah[row * H_DIM + col]           = __float2bfloat16(acc[ms][ns][0] + b10);
                    g_Ah[row * H_DIM + col + 1]       = __float2bfloat16(acc[ms][ns][1] + b11);
                    g_Ah[(row + 8) * H_DIM + col]     = __float2bfloat16(acc[ms][ns][2] + b10);
                    g_Ah[(row + 8) * H_DIM + col + 1] = __float2bfloat16(acc[ms][ns][3] + b11);
                } else {
                    g_Bh[row * H_DIM + col]           = __float2bfloat16(acc[ms][ns][0]);
                    g_Bh[row * H_DIM + col + 1]       = __float2bfloat16(acc[ms][ns][1]);
                    g_Bh[(row + 8) * H_DIM + col]     = __float2bfloat16(acc[ms][ns][2]);
                    g_Bh[(row + 8) * H_DIM + col + 1] = __float2bfloat16(acc[ms][ns][3]);
                }
            }
    } else {
        // ---- S epilogue: per-i partial denom / pair-logit-sum over 128 j's --
        #pragma unroll
        for (int ms = 0; ms < 2; ++ms) {
            float d0 = 0.f, l0 = 0.f, d1 = 0.f, l1 = 0.f;
            int row0 = mw * 32 + ms * 16 + g;
            int ig0 = m0 + row0;
            #pragma unroll
            for (int ns = 0; ns < 4; ++ns)
                #pragma unroll
                for (int q = 0; q < 4; ++q) {
                    int jg = n0 + nw * 32 + ns * 8 + 2 * tg + (q & 1);
                    int ig = ig0 + ((q >= 2) ? 8 : 0);
                    float v = 2.0f * acc[ms][ns][q];
                    float e = (jg != ig) ? expf(v) : 0.f;
                    float lv = (jg > ig && jg < N_CON) ? v : 0.f;
                    if (q < 2) { d0 += e; l0 += lv; } else { d1 += e; l1 += lv; }
                }
            d0 += __shfl_xor_sync(0xffffffffu, d0, 1); d0 += __shfl_xor_sync(0xffffffffu, d0, 2);
            l0 += __shfl_xor_sync(0xffffffffu, l0, 1); l0 += __shfl_xor_sync(0xffffffffu, l0, 2);
            d1 += __shfl_xor_sync(0xffffffffu, d1, 1); d1 += __shfl_xor_sync(0xffffffffu, d1, 2);
            l1 += __shfl_xor_sync(0xffffffffu, l1, 1); l1 += __shfl_xor_sync(0xffffffffu, l1, 2);
            if (tg == 0) {
                denred[nw * 64 + row0]     = d0;  lsred[nw * 64 + row0]     = l0;
                denred[nw * 64 + row0 + 8] = d1;  lsred[nw * 64 + row0 + 8] = l1;
            }
        }
        __syncthreads();
        if (tid < 64) {
            int jt = (b - 20) & 3;
            float den = 0.f, ls = 0.f;
            #pragma unroll
            for (int w = 0; w < 4; ++w) { den += denred[w * 64 + tid]; ls += lsred[w * 64 + tid]; }
            g_denp[jt][m0 + tid] = den;
            g_lsp[jt][m0 + tid]  = ls;
        }
    }
}

// ---------------- kernel 3: fused pair MLP + BCE (512 thr, full N) ----------
// Block (c, i): 128 pairs (i, j), j in [128c, 128c+128). Full h2 (256 n) in one
// block; epilogue computes final logits + BCE, writes one partial per block.
#define SM_STRIDE 264   // 256 + 8 bf16 pad -> conflict-free fragment LDS
#define PAIR3_SMEM ((128 + 256) * SM_STRIDE * 2)
__global__ __launch_bounds__(512, 1) void pair_mma_kernel(const float* __restrict__ b2,
                                                          const float* __restrict__ W3,
                                                          const float* __restrict__ b3) {
    extern __shared__ __nv_bfloat16 sm[];
    __nv_bfloat16* h1s = sm;                         // [128][264]
    __nv_bfloat16* w2s = sm + 128 * SM_STRIDE;       // [256][264]
    __shared__ float wpart[4][128];                  // per-N-warp logit partials
    __shared__ float bred[16];

    int c = blockIdx.x, i = blockIdx.y;
    int tid = threadIdx.x, lane = tid & 31, wid = tid >> 5;
    int j0 = c * 128;

    // ---- build h1 tile: h1[r][k] = relu(Ah[i][k] + Bh[j0+r][k]) ----
    const __nv_bfloat162* Arow = (const __nv_bfloat162*)(g_Ah + i * H_DIM);
    for (int e = tid; e < 128 * 128; e += 512) {
        int r = e >> 7, kp = e & 127;
        __nv_bfloat162 av = Arow[kp];
        __nv_bfloat162 bv = ((const __nv_bfloat162*)(g_Bh + (j0 + r) * H_DIM))[kp];
        float x = fmaxf(__bfloat162float(av.x) + __bfloat162float(bv.x), 0.f);
        float y = fmaxf(__bfloat162float(av.y) + __bfloat162float(bv.y), 0.f);
        *(__nv_bfloat162*)(h1s + r * SM_STRIDE + 2 * kp) = __floats2bfloat162_rn(x, y);
    }
    // ---- stage full W2: 256 rows x 32 uint4 ----
    for (int e = tid; e < 256 * 32; e += 512) {
        int r = e >> 5, q = e & 31;
        uint4 v = ((const uint4*)(g_W2h + r * H_DIM))[q];
        *(uint4*)(w2s + r * SM_STRIDE + q * 8) = v;
    }
    __syncthreads();

    int mw = wid & 3, nw = wid >> 2;   // 4 warps in M (32 rows), 4 in N (64 cols)
    int g = lane >> 2, tg = lane & 3;

    float acc[2][8][4];
    #pragma unroll
    for (int ms = 0; ms < 2; ++ms)
        #pragma unroll
        for (int ns = 0; ns < 8; ++ns)
            #pragma unroll
            for (int q = 0; q < 4; ++q) acc[ms][ns][q] = 0.f;

    #pragma unroll 2
    for (int ks = 0; ks < 16; ++ks) {
        int k0 = ks * 16;
        unsigned a[2][4];
        #pragma unroll
        for (int ms = 0; ms < 2; ++ms) {
            const __nv_bfloat16* base0 = h1s + (mw * 32 + ms * 16 + g) * SM_STRIDE + k0 + 2 * tg;
            a[ms][0] = *(const unsigned*)(base0);
            a[ms][1] = *(const unsigned*)(base0 + 8 * SM_STRIDE);
            a[ms][2] = *(const unsigned*)(base0 + 8);
            a[ms][3] = *(const unsigned*)(base0 + 8 * SM_STRIDE + 8);
        }
        unsigned bfr[8][2];
        #pragma unroll
        for (int ns = 0; ns < 8; ++ns) {
            const __nv_bfloat16* bb = w2s + (nw * 64 + ns * 8 + g) * SM_STRIDE + k0 + 2 * tg;
            bfr[ns][0] = *(const unsigned*)(bb);
            bfr[ns][1] = *(const unsigned*)(bb + 8);
        }
        #pragma unroll
        for (int ms = 0; ms < 2; ++ms)
            #pragma unroll
            for (int ns = 0; ns < 8; ++ns)
                asm volatile(
                    "mma.sync.aligned.m16n8k16.row.col.f32.bf16.bf16.f32 "
                    "{%0,%1,%2,%3}, {%4,%5,%6,%7}, {%8,%9}, {%0,%1,%2,%3};"
                    : "+f"(acc[ms][ns][0]), "+f"(acc[ms][ns][1]),
                      "+f"(acc[ms][ns][2]), "+f"(acc[ms][ns][3])
                    : "r"(a[ms][0]), "r"(a[ms][1]), "r"(a[ms][2]), "r"(a[ms][3]),
                      "r"(bfr[ns][0]), "r"(bfr[ns][1]));
    }

    // ---- epilogue: relu(h2 + b2) dot W3 over this warp's 64 n, per row ----
    #pragma unroll
    for (int ms = 0; ms < 2; ++ms) {
        float rs0 = 0.f, rs1 = 0.f;
        #pragma unroll
        for (int ns = 0; ns < 8; ++ns) {
            int n0 = nw * 64 + ns * 8 + 2 * tg;
            float b20 = __ldg(b2 + n0), b21 = __ldg(b2 + n0 + 1);
            float w30 = __ldg(W3 + n0), w31 = __ldg(W3 + n0 + 1);
            rs0 += fmaxf(acc[ms][ns][0] + b20, 0.f) * w30
                 + fmaxf(acc[ms][ns][1] + b21, 0.f) * w31;
            rs1 += fmaxf(acc[ms][ns][2] + b20, 0.f) * w30
                 + fmaxf(acc[ms][ns][3] + b21, 0.f) * w31;
        }
        rs0 += __shfl_xor_sync(0xffffffffu, rs0, 1);
        rs0 += __shfl_xor_sync(0xffffffffu, rs0, 2);
        rs1 += __shfl_xor_sync(0xffffffffu, rs1, 1);
        rs1 += __shfl_xor_sync(0xffffffffu, rs1, 2);
        if (tg == 0) {
            int r = mw * 32 + ms * 16 + g;
            wpart[nw][r]     = rs0;
            wpart[nw][r + 8] = rs1;
        }
    }
    __syncthreads();

    // ---- fused BCE over this block's 128 pairs ----
    float s = 0.f;
    if (tid < 128) {
        int j = j0 + tid;
        if (j > i) {
            float l = b3[0] + wpart[0][tid] + wpart[1][tid] + wpart[2][tid] + wpart[3][tid];
            float y = (j < M_POS) ? 1.f : 0.f;
            s = fmaxf(l, 0.f) - l * y + log1pf(expf(-fabsf(l)));
        }
    }
    #pragma unroll
    for (int o = 16; o; o >>= 1) s += __shfl_xor_sync(0xffffffffu, s, o);
    if (lane == 0) bred[wid] = s;
    __syncthreads();
    if (tid == 0) {
        float t = 0.f;
        #pragma unroll
        for (int w = 0; w < 16; ++w) t += bred[w];
        g_eblk[i * 4 + c] = t;
    }
}

// ---------------- kernel 4: final reduction (closs from partials + eloss) ----
__global__ __launch_bounds__(128) void final_kernel(float* __restrict__ out) {
    __shared__ float red[128];
    int tid = threadIdx.x;   // one thread per i
    float den = 0.f, ls = 0.f;
    #pragma unroll
    for (int t = 0; t < 4; ++t) { den += g_denp[t][tid]; ls += g_lsp[t][tid]; }
    float cpart = (float)(N_CON - 1 - tid) * logf(den) - ls;
    red[tid] = cpart;
    __syncthreads();
    for (int s = 64; s; s >>= 1) {
        if (tid < s) red[tid] += red[tid + s];
        __syncthreads();
    }
    float csum = red[0];
    __syncthreads();
    float e = 0.f;
    #pragma unroll
    for (int t = 0; t < 4; ++t) e += g_eblk[tid * 4 + t];
    red[tid] = e;
    __syncthreads();
    for (int s = 64; s; s >>= 1) {
        if (tid < s) red[tid] += red[tid + s];
        __syncthreads();
    }
    if (tid == 0) {
        float closs = -1.984375f * csum;          // -2*(n-1)/n * closs_sum
        out[0] = closs + red[0] * (1.0f / NPAIRS);
    }
}

// ---------------- launch -----------------------------------------------------
extern "C" void kernel_launch(void* const* d_in, const int* in_sizes, int n_in,
                              void* d_out, int out_size) {
    const float* emb = (const float*)d_in[0];
    const float* W1  = (const float*)d_in[1];
    const float* b1  = (const float*)d_in[2];
    const float* W2  = (const float*)d_in[3];
    const float* b2  = (const float*)d_in[4];
    const float* W3  = (const float*)d_in[5];
    const float* b3  = (const float*)d_in[6];
    float* out = (float*)d_out;

    cudaFuncSetAttribute(mid_kernel, cudaFuncAttributeMaxDynamicSharedMemorySize, MID_SMEM);
    cudaFuncSetAttribute(pair_mma_kernel, cudaFuncAttributeMaxDynamicSharedMemorySize, PAIR3_SMEM);

    prep_norm_kernel<<<B_ROWS + 448, 256>>>(emb, W1, W2);
    mid_kernel<<<28, 256, MID_SMEM>>>(b1);
    pair_mma_kernel<<<dim3(4, N_CON), 512, PAIR3_SMEM>>>(b2, W3, b3);
    final_kernel<<<1, 128>>>(out);
}